// round 1
// baseline (speedup 1.0000x reference)
#include <cuda_runtime.h>

#define F 256
#define TOTAL_ROWS (32 * 4096)      // B*T = 131072
#define EPS 1e-5f

// Scratch (no cudaMalloc allowed)
__device__ float              g_sum[F];
__device__ float              g_sumsq[F];
__device__ unsigned long long g_count;
__device__ float              g_scale[F];
__device__ float              g_bias[F];

// ---------------------------------------------------------------------------
// Kernel 0: zero accumulators (graph replays must be idempotent)
// ---------------------------------------------------------------------------
__global__ void init_kernel() {
    int t = threadIdx.x;
    g_sum[t]   = 0.0f;
    g_sumsq[t] = 0.0f;
    if (t == 0) g_count = 0ULL;
}

// ---------------------------------------------------------------------------
// Kernel 1: per-feature sum / sumsq over masked rows.
// blockDim = 256 (thread == feature). All threads of a block walk the same
// rows, so the mask branch is block-uniform: unmasked rows cost only a
// broadcast 4B mask load — their 1 KB of x is never fetched (~50% read
// savings on pass 1). Unroll by 4 rows for MLP.
// ---------------------------------------------------------------------------
__global__ void __launch_bounds__(256) stats_kernel(const float* __restrict__ x,
                                                    const int*   __restrict__ mask) {
    const int f  = threadIdx.x;
    const int rows_per_block = TOTAL_ROWS / gridDim.x;
    const int row0 = blockIdx.x * rows_per_block;

    float acc = 0.0f, acc2 = 0.0f;
    int   cnt = 0;

    int r = row0;
#pragma unroll 1
    for (; r + 4 <= row0 + rows_per_block; r += 4) {
        int m0 = mask[r + 0];
        int m1 = mask[r + 1];
        int m2 = mask[r + 2];
        int m3 = mask[r + 3];
        if (m0 > 0) { float v = x[(size_t)(r + 0) * F + f]; acc += v; acc2 += v * v; cnt++; }
        if (m1 > 0) { float v = x[(size_t)(r + 1) * F + f]; acc += v; acc2 += v * v; cnt++; }
        if (m2 > 0) { float v = x[(size_t)(r + 2) * F + f]; acc += v; acc2 += v * v; cnt++; }
        if (m3 > 0) { float v = x[(size_t)(r + 3) * F + f]; acc += v; acc2 += v * v; cnt++; }
    }
    for (; r < row0 + rows_per_block; ++r) {
        if (mask[r] > 0) { float v = x[(size_t)r * F + f]; acc += v; acc2 += v * v; cnt++; }
    }

    atomicAdd(&g_sum[f],   acc);
    atomicAdd(&g_sumsq[f], acc2);
    if (f == 0) atomicAdd(&g_count, (unsigned long long)cnt);
}

// ---------------------------------------------------------------------------
// Kernel 2: finalize — fold mean/var/gamma/beta into a per-feature affine
// (scale, bias) so the apply pass is a single FMA per element.
// ---------------------------------------------------------------------------
__global__ void finalize_kernel(const float* __restrict__ gamma,
                                const float* __restrict__ beta) {
    int f = threadIdx.x;
    float cnt  = (float)g_count;
    float mean = g_sum[f] / cnt;
    float var  = g_sumsq[f] / cnt - mean * mean;
    float s    = rsqrtf(var + EPS) * gamma[f];
    g_scale[f] = s;
    g_bias[f]  = beta[f] - mean * s;
}

// ---------------------------------------------------------------------------
// Kernel 3: apply. float4-vectorized; one warp spans half a row (32*16B =
// 512B of a 1KB row), so the mask branch is warp-uniform and the mask load
// is a broadcast L1 hit.
// ---------------------------------------------------------------------------
__global__ void __launch_bounds__(256) apply_kernel(const float* __restrict__ x,
                                                    const int*   __restrict__ mask,
                                                    float*       __restrict__ out) {
    const size_t i = (size_t)blockIdx.x * blockDim.x + threadIdx.x;  // float4 index
    const float4* __restrict__ x4 = (const float4*)x;
    float4* __restrict__ out4 = (float4*)out;

    const int row = (int)(i >> 6);       // 64 float4 per row
    const int f4  = (int)(i & 63);

    float4 v = x4[i];
    if (mask[row] > 0) {
        const float4* s4 = (const float4*)g_scale;
        const float4* b4 = (const float4*)g_bias;
        float4 s = s4[f4];
        float4 b = b4[f4];
        v.x = fmaf(v.x, s.x, b.x);
        v.y = fmaf(v.y, s.y, b.y);
        v.z = fmaf(v.z, s.z, b.z);
        v.w = fmaf(v.w, s.w, b.w);
    }
    out4[i] = v;
}

// ---------------------------------------------------------------------------
extern "C" void kernel_launch(void* const* d_in, const int* in_sizes, int n_in,
                              void* d_out, int out_size) {
    const float* x     = (const float*)d_in[0];
    const int*   mask  = (const int*)d_in[1];
    const float* gamma = (const float*)d_in[2];
    const float* beta  = (const float*)d_in[3];
    float*       out   = (float*)d_out;

    init_kernel<<<1, 256>>>();

    // 1024 blocks x 128 rows: ~7 blocks/SM, per-thread partials <=128 elems,
    // 512K spread-address atomics (~1 us).
    stats_kernel<<<1024, 256>>>(x, mask);

    finalize_kernel<<<1, 256>>>(gamma, beta);

    // 32*4096*256 / 4 = 8,388,608 float4 -> 32768 blocks of 256
    apply_kernel<<<32768, 256>>>(x, mask, out);
}